// round 8
// baseline (speedup 1.0000x reference)
#include <cuda_runtime.h>

#define NROWS   2048
#define NCOLS   9605
#define ROWS_PB 4
#define NBLK    (NROWS / ROWS_PB)          // 512
#define NTHR    512
#define V4_PB   (ROWS_PB * NCOLS / 4)      // 9605 float4s per block (exact)
#define CAPS    320
#define CLIPV   0.05f
#define P_TH    0.90f                       // sigmoid(2.197); E[cand/row] ~134

__device__ double       g_part[NBLK];
__device__ unsigned int g_done;             // static zero; reset by last block

// base*w for one element; returns bw, outputs sigmoid p
__device__ __forceinline__ float bw_of(float xv, float yv, float& p_out) {
    float e    = __expf(-xv);
    float p    = __fdividef(1.f, 1.f + e);
    p_out      = p;
    float xneg = fminf(1.f - p + CLIPV, 1.f);
    float t    = fmaxf(p - CLIPV, 0.f);          // 1 - xneg
    float t2   = t * t;
    float t4   = t2 * t2;
    bool  pos  = yv > 0.5f;
    float lg   = __logf(fmaxf(pos ? p : xneg, 1e-8f));
    float w    = pos ? (1.f - p) : t4;           // gamma_pos=1, gamma_neg=4
    return lg * w;
}

__device__ __forceinline__ unsigned long long mk_key(float p, int col) {
    return ((unsigned long long)__float_as_uint(p) << 32) |
           (unsigned long long)(0xFFFFFFFFu - (unsigned)col);
}

__device__ __forceinline__ void ins10(unsigned long long* tk, float* tb,
                                      unsigned long long key, float bw) {
    if (key > tk[9]) {
        tk[9] = key; tb[9] = bw;
#pragma unroll
        for (int i = 9; i > 0; i--) {
            if (tk[i] > tk[i - 1]) {
                unsigned long long k0 = tk[i - 1]; tk[i - 1] = tk[i]; tk[i] = k0;
                float b0 = tb[i - 1]; tb[i - 1] = tb[i]; tb[i] = b0;
            }
        }
    }
}

// ---------------------------------------------------------------------------
// One block = 4 rows: stream sum + candidate harvest (smem) + flags + top-10 +
// rank corrections. Last finishing block reduces all per-block partials.
__global__ void __launch_bounds__(NTHR)
k_main(const float* __restrict__ x, const float* __restrict__ y,
       const int* __restrict__ ci, const int* __restrict__ ri,
       const int* __restrict__ di, const int* __restrict__ wl,
       float* __restrict__ out) {
    const int tid = threadIdx.x;
    const int bid = blockIdx.x;
    const size_t base = (size_t)bid * ROWS_PB * NCOLS;

    __shared__ int                s_cnt[ROWS_PB];
    __shared__ int                s_flags[ROWS_PB];
    __shared__ unsigned long long s_key[ROWS_PB][CAPS + 1];
    __shared__ float              s_bw[ROWS_PB][CAPS + 1];
    __shared__ float              s_corr[ROWS_PB];
    __shared__ float              s_warp[NTHR / 32];
    __shared__ int                s_last;

    if (tid < ROWS_PB) { s_cnt[tid] = 0; s_flags[tid] = 0; }
    __syncthreads();

    const float4* __restrict__ x4 = reinterpret_cast<const float4*>(x + base);
    const float4* __restrict__ y4 = reinterpret_cast<const float4*>(y + base);

    float sum = 0.f;
#pragma unroll 4
    for (int v = tid; v < V4_PB; v += NTHR) {
        float4 xv = x4[v];
        float4 yv = y4[v];
        float xs[4] = {xv.x, xv.y, xv.z, xv.w};
        float ys[4] = {yv.x, yv.y, yv.z, yv.w};
        int gi0 = v * 4;
#pragma unroll
        for (int k = 0; k < 4; k++) {
            float p;
            float bw = bw_of(xs[k], ys[k], p);
            sum += bw;
            if (p > P_TH) {                               // ~1.4% of elements
                int gi = gi0 + k;
                int rl = gi / NCOLS;                      // 0..3 (const div)
                int col = gi - rl * NCOLS;
                int slot = atomicAdd(&s_cnt[rl], 1);
                if (slot < CAPS) {
                    s_key[rl][slot] = mk_key(p, col);
                    s_bw[rl][slot]  = bw;
                }
            }
        }
    }

    // gt-whitelist flags: 170 probe indices x 4 rows (rows still L2-hot)
    for (int i = tid; i < 170 * ROWS_PB; i += NTHR) {
        int r = i / 170, k = i - r * 170;
        int idx = (k < 30) ? ci[k] : (k < 100) ? ri[k - 30] : di[k - 100];
        if (y[base + (size_t)r * NCOLS + idx] > 0.5f) {
            int bit = (k < 30) ? 1 : (k < 100) ? 2 : 4;
            atomicOr(&s_flags[r], bit);
        }
    }
    __syncthreads();

    // per-row selection + rank logic (threads 0..3, one row each)
    if (tid < ROWS_PB) {
        const int r = tid;
        unsigned long long tk[10];
        float tb[10];
#pragma unroll
        for (int i = 0; i < 10; i++) { tk[i] = 0ULL; tb[i] = 0.f; }

        int n = s_cnt[r];
        if (n < 10 || n > CAPS) {
            // exact fallback: serial rescan of the row (astronomically rare)
            const float* xr = x + base + (size_t)r * NCOLS;
            const float* yr = y + base + (size_t)r * NCOLS;
            for (int c = 0; c < NCOLS; c++) {
                float p;
                float bw = bw_of(xr[c], yr[c], p);
                ins10(tk, tb, mk_key(p, c), bw);
            }
        } else {
            for (int i = 0; i < n; i++) ins10(tk, tb, s_key[r][i], s_bw[r][i]);
        }

        int fl = s_flags[r];
        bool has1 = fl & 1, has2 = fl & 2, has3 = fl & 4;
        bool only4 = !(has1 || has2 || has3);
        bool found = false;
        float fac[10];
#pragma unroll
        for (int q = 0; q < 10; q++) {
            int j = (int)(0xFFFFFFFFu - (unsigned)(tk[q] & 0xFFFFFFFFULL));
            int g = wl[j];
            bool in_map = g > 0;
            bool in_gt  = ((g == 1) && has1) || ((g == 2) && has2) ||
                          ((g == 3) && has3) || ((g == 4) && only4);
            float f = (in_map && only4) ? 0.5f : 1.f;     // ALPHA_OTHER
            if (in_map && !in_gt && !found) f *= 2.f;     // ALPHA1 (first-miss)
            fac[q] = f;
            found = found || (in_map && in_gt);
        }
        float extra = found ? 1.f : 2.f;                  // final ALPHA1 pass
        float corr = 0.f;
#pragma unroll
        for (int q = 0; q < 10; q++)
            corr += tb[q] * (fac[q] * extra - 1.f);       // bw*(mult-1)
        s_corr[r] = corr;
    }

    // block reduction of stream sum + corrections -> per-block double partial
#pragma unroll
    for (int off = 16; off > 0; off >>= 1)
        sum += __shfl_down_sync(0xFFFFFFFFu, sum, off);
    int lane = tid & 31, wid = tid >> 5;
    if (lane == 0) s_warp[wid] = sum;
    __syncthreads();
    if (tid == 0) {
        float b = 0.f;
#pragma unroll
        for (int i = 0; i < NTHR / 32; i++) b += s_warp[i];
        double tot = (double)b;
#pragma unroll
        for (int r = 0; r < ROWS_PB; r++) tot += (double)s_corr[r];
        g_part[bid] = tot;
        __threadfence();
        unsigned t = atomicAdd(&g_done, 1u);
        s_last = (t == NBLK - 1) ? 1 : 0;
    }
    __syncthreads();

    // last finishing block: reduce all 512 partials (deterministic order)
    if (s_last) {
        __threadfence();
        double d = g_part[tid];                           // NTHR == NBLK
        __shared__ double s_dw[NTHR / 32];
#pragma unroll
        for (int off = 16; off > 0; off >>= 1)
            d += __shfl_down_sync(0xFFFFFFFFu, d, off);
        if (lane == 0) s_dw[wid] = d;
        __syncthreads();
        if (tid == 0) {
            double tsum = 0.0;
#pragma unroll
            for (int i = 0; i < NTHR / 32; i++) tsum += s_dw[i];
            out[0] = (float)(-tsum);
            g_done = 0;                                   // reset for replay
        }
    }
}

extern "C" void kernel_launch(void* const* d_in, const int* in_sizes, int n_in,
                              void* d_out, int out_size) {
    const float* x  = (const float*)d_in[0];
    const float* y  = (const float*)d_in[1];
    const int*   ci = (const int*)d_in[2];
    const int*   ri = (const int*)d_in[3];
    const int*   di = (const int*)d_in[4];
    const int*   wl = (const int*)d_in[5];

    k_main<<<NBLK, NTHR>>>(x, y, ci, ri, di, wl, (float*)d_out);
}

// round 10
// speedup vs baseline: 1.5595x; 1.5595x over previous
#include <cuda_runtime.h>

#define NROWS   2048
#define NCOLS   9605
#define ROWS_PB 4
#define NBLK    (NROWS / ROWS_PB)          // 512
#define NTHR    256
#define V4_PB   (ROWS_PB * NCOLS / 4)      // 9605 float4s per block (exact)
#define VMAIN   9216                        // 9 iters x (4 x 256)
#define CAPS    160
#define CLIPV   0.05f
#define X_TH    2.58f                       // p_th ~0.9296; E[cand/row] ~47

__device__ double       g_part[NBLK];
__device__ unsigned int g_done;             // static zero; last block resets

// base*w for one element (identical math to hot loop)
__device__ __forceinline__ float bw_of(float xv, float yv) {
    float e    = __expf(-xv);
    float p    = __fdividef(1.f, 1.f + e);
    float xneg = fminf(1.f - p + CLIPV, 1.f);
    float t    = fmaxf(p - CLIPV, 0.f);
    float t4   = (t * t) * (t * t);
    bool  pos  = yv > 0.5f;
    float arg  = fmaxf(pos ? p : xneg, 1e-8f);
    float w    = pos ? (1.f - p) : t4;
    return __logf(arg) * w;
}

__device__ __forceinline__ unsigned long long mk_key(float p, int col) {
    return ((unsigned long long)__float_as_uint(p) << 32) |
           (unsigned long long)(0xFFFFFFFFu - (unsigned)col);
}

__device__ __forceinline__ void ins10(unsigned long long* tk,
                                      unsigned long long key) {
    if (key > tk[9]) {
        tk[9] = key;
#pragma unroll
        for (int i = 9; i > 0; i--)
            if (tk[i] > tk[i - 1]) {
                unsigned long long k0 = tk[i - 1];
                tk[i - 1] = tk[i]; tk[i] = k0;
            }
    }
}

// process 4 elements of one float4 pair
__device__ __forceinline__ void proc4(float4 xv, float4 yv, int gi0,
                                      float& sum, int* cnt,
                                      unsigned long long* keys) {
    float xs[4] = {xv.x, xv.y, xv.z, xv.w};
    float ys[4] = {yv.x, yv.y, yv.z, yv.w};
#pragma unroll
    for (int k = 0; k < 4; k++) {
        float xvk  = xs[k];
        float e    = __expf(-xvk);
        float p    = __fdividef(1.f, 1.f + e);
        float xneg = fminf(1.f - p + CLIPV, 1.f);
        float t    = fmaxf(p - CLIPV, 0.f);
        float t4   = (t * t) * (t * t);
        bool  pos  = ys[k] > 0.5f;
        float arg  = fmaxf(pos ? p : xneg, 1e-8f);
        float w    = pos ? (1.f - p) : t4;
        sum += __logf(arg) * w;
        if (xvk > X_TH) {                         // rare (~0.5% of elements)
            int gi  = gi0 + k;
            int rl  = gi / NCOLS;                 // 0..3 (const div)
            int col = gi - rl * NCOLS;
            int slot = atomicAdd(&cnt[rl], 1);
            if (slot < CAPS)
                keys[rl * (CAPS + 1) + slot] = mk_key(p, col);
        }
    }
}

// ---------------------------------------------------------------------------
__global__ void __launch_bounds__(NTHR, 4)
k_main(const float* __restrict__ x, const float* __restrict__ y,
       const int* __restrict__ ci, const int* __restrict__ ri,
       const int* __restrict__ di, const int* __restrict__ wl,
       float* __restrict__ out) {
    const int tid = threadIdx.x;
    const int bid = blockIdx.x;
    const size_t base = (size_t)bid * ROWS_PB * NCOLS;

    __shared__ int                s_cnt[ROWS_PB];
    __shared__ int                s_flags[ROWS_PB];
    __shared__ unsigned long long s_key[ROWS_PB * (CAPS + 1)];
    __shared__ float              s_corr[ROWS_PB];
    __shared__ float              s_warp[NTHR / 32];
    __shared__ int                s_last;

    if (tid < ROWS_PB) { s_cnt[tid] = 0; s_flags[tid] = 0; }
    __syncthreads();

    const float4* __restrict__ x4 = reinterpret_cast<const float4*>(x + base);
    const float4* __restrict__ y4 = reinterpret_cast<const float4*>(y + base);

    float sum = 0.f;

    // main: 9 iterations, 4 front-batched float4-pairs each (deep MLP)
#pragma unroll 1
    for (int it = 0; it < 9; it++) {
        int v = tid + it * (4 * NTHR);
        float4 xa = x4[v];
        float4 xb = x4[v + NTHR];
        float4 xc = x4[v + 2 * NTHR];
        float4 xd = x4[v + 3 * NTHR];
        float4 ya = y4[v];
        float4 yb = y4[v + NTHR];
        float4 yc = y4[v + 2 * NTHR];
        float4 yd = y4[v + 3 * NTHR];
        proc4(xa, ya, v * 4,              sum, s_cnt, s_key);
        proc4(xb, yb, (v + NTHR) * 4,     sum, s_cnt, s_key);
        proc4(xc, yc, (v + 2 * NTHR) * 4, sum, s_cnt, s_key);
        proc4(xd, yd, (v + 3 * NTHR) * 4, sum, s_cnt, s_key);
    }
    // tail: v in [9216, 9605)
    for (int v = VMAIN + tid; v < V4_PB; v += NTHR) {
        float4 xa = x4[v];
        float4 ya = y4[v];
        proc4(xa, ya, v * 4, sum, s_cnt, s_key);
    }

    // gt-whitelist flags: 170 probes x 4 rows
    for (int i = tid; i < 170 * ROWS_PB; i += NTHR) {
        int r = i / 170, k = i - r * 170;
        int idx = (k < 30) ? ci[k] : (k < 100) ? ri[k - 30] : di[k - 100];
        if (y[base + (size_t)r * NCOLS + idx] > 0.5f) {
            int bit = (k < 30) ? 1 : (k < 100) ? 2 : 4;
            atomicOr(&s_flags[r], bit);
        }
    }
    __syncthreads();

    // per-row: exact top-10 + sequential rank logic + corrections
    if (tid < ROWS_PB) {
        const int r = tid;
        const float* xr = x + base + (size_t)r * NCOLS;
        const float* yr = y + base + (size_t)r * NCOLS;
        unsigned long long tk[10];
#pragma unroll
        for (int i = 0; i < 10; i++) tk[i] = 0ULL;

        int n = s_cnt[r];
        if (n < 10 || n > CAPS) {
            // exact fallback (astronomically rare): serial rescan of the row
            for (int c = 0; c < NCOLS; c++) {
                float e = __expf(-xr[c]);
                float p = __fdividef(1.f, 1.f + e);
                ins10(tk, mk_key(p, c));
            }
        } else {
            const unsigned long long* kr = s_key + r * (CAPS + 1);
            for (int i = 0; i < n; i++) ins10(tk, kr[i]);
        }

        int fl = s_flags[r];
        bool has1 = fl & 1, has2 = fl & 2, has3 = fl & 4;
        bool only4 = !(has1 || has2 || has3);
        bool found = false;
        float fac[10];
        int   idx10[10];
#pragma unroll
        for (int q = 0; q < 10; q++) {
            int j = (int)(0xFFFFFFFFu - (unsigned)(tk[q] & 0xFFFFFFFFULL));
            int g = wl[j];
            bool in_map = g > 0;
            bool in_gt  = ((g == 1) && has1) || ((g == 2) && has2) ||
                          ((g == 3) && has3) || ((g == 4) && only4);
            float f = (in_map && only4) ? 0.5f : 1.f;     // ALPHA_OTHER
            if (in_map && !in_gt && !found) f *= 2.f;     // ALPHA1 (first-miss)
            fac[q] = f;
            idx10[q] = j;
            found = found || (in_map && in_gt);
        }
        float extra = found ? 1.f : 2.f;                  // final ALPHA1 pass
        float corr = 0.f;
#pragma unroll
        for (int q = 0; q < 10; q++) {
            int j = idx10[q];
            corr += bw_of(xr[j], yr[j]) * (fac[q] * extra - 1.f);
        }
        s_corr[r] = corr;
    }

    // block reduction -> per-block double partial
#pragma unroll
    for (int off = 16; off > 0; off >>= 1)
        sum += __shfl_down_sync(0xFFFFFFFFu, sum, off);
    int lane = tid & 31, wid = tid >> 5;
    if (lane == 0) s_warp[wid] = sum;
    __syncthreads();
    if (tid == 0) {
        float b = 0.f;
#pragma unroll
        for (int i = 0; i < NTHR / 32; i++) b += s_warp[i];
        double tot = (double)b;
#pragma unroll
        for (int r = 0; r < ROWS_PB; r++) tot += (double)s_corr[r];
        g_part[bid] = tot;
        __threadfence();
        unsigned t = atomicAdd(&g_done, 1u);
        s_last = (t == NBLK - 1) ? 1 : 0;
    }
    __syncthreads();

    // last finishing block reduces all 512 partials (deterministic)
    if (s_last) {
        __threadfence();
        double d = g_part[tid] + g_part[tid + NTHR];      // 512 partials
        __shared__ double s_dw[NTHR / 32];
#pragma unroll
        for (int off = 16; off > 0; off >>= 1)
            d += __shfl_down_sync(0xFFFFFFFFu, d, off);
        if (lane == 0) s_dw[wid] = d;
        __syncthreads();
        if (tid == 0) {
            double tsum = 0.0;
#pragma unroll
            for (int i = 0; i < NTHR / 32; i++) tsum += s_dw[i];
            out[0] = (float)(-tsum);
            g_done = 0;                                   // reset for replay
        }
    }
}

extern "C" void kernel_launch(void* const* d_in, const int* in_sizes, int n_in,
                              void* d_out, int out_size) {
    const float* x  = (const float*)d_in[0];
    const float* y  = (const float*)d_in[1];
    const int*   ci = (const int*)d_in[2];
    const int*   ri = (const int*)d_in[3];
    const int*   di = (const int*)d_in[4];
    const int*   wl = (const int*)d_in[5];

    k_main<<<NBLK, NTHR>>>(x, y, ci, ri, di, wl, (float*)d_out);
}